// round 4
// baseline (speedup 1.0000x reference)
#include <cuda_runtime.h>
#include <cstdint>

#define NS 512
#define NV 32000
#define NB 16
#define NT 128

// ---- scratch (no cudaMalloc allowed) ----
__device__ float g_lse_em[NS];
__device__ float g_pi[NS];
__device__ float g_PT[NS * NS];          // PT[c][s] = softmax(tm)[s][c]
__device__ float g_E[NB * NT * NS];      // E[b][t][s] = exp(log_em[s, x_bt])
__device__ float g_L[NB];                // per-batch log-likelihood
__device__ float g_X[2][NB][NS];         // per-group exchange buffers (double)
__device__ unsigned g_cnt[NB * 64];      // per-group barrier counters, 256B apart

// ===================== K1: row logsumexp of em [512, 32000] =====================
__global__ void k_lse_em(const float* __restrict__ em) {
    const int row = blockIdx.x;
    const float4* r = (const float4*)(em + (size_t)row * NV);
    const int n4 = NV / 4;  // 8000

    __shared__ float sm[8];

    float m = -1e30f;
    for (int i = threadIdx.x; i < n4; i += blockDim.x) {
        float4 x = r[i];
        m = fmaxf(m, fmaxf(fmaxf(x.x, x.y), fmaxf(x.z, x.w)));
    }
    #pragma unroll
    for (int o = 16; o; o >>= 1) m = fmaxf(m, __shfl_xor_sync(~0u, m, o));
    if ((threadIdx.x & 31) == 0) sm[threadIdx.x >> 5] = m;
    __syncthreads();
    if (threadIdx.x < 32) {
        float mm = (threadIdx.x < (blockDim.x >> 5)) ? sm[threadIdx.x] : -1e30f;
        #pragma unroll
        for (int o = 4; o; o >>= 1) mm = fmaxf(mm, __shfl_xor_sync(~0u, mm, o));
        if (threadIdx.x == 0) sm[0] = mm;
    }
    __syncthreads();
    m = sm[0];
    __syncthreads();

    float s = 0.f;
    for (int i = threadIdx.x; i < n4; i += blockDim.x) {
        float4 x = r[i];
        s += __expf(x.x - m) + __expf(x.y - m) + __expf(x.z - m) + __expf(x.w - m);
    }
    #pragma unroll
    for (int o = 16; o; o >>= 1) s += __shfl_xor_sync(~0u, s, o);
    if ((threadIdx.x & 31) == 0) sm[threadIdx.x >> 5] = s;
    __syncthreads();
    if (threadIdx.x == 0) {
        float tot = 0.f;
        for (int wi = 0; wi < (blockDim.x >> 5); wi++) tot += sm[wi];
        g_lse_em[row] = m + __logf(tot);
    }
}

// ===================== K2: P^T = softmax(tm) transposed; pi = softmax(p) ========
__global__ void k_tm_pi(const float* __restrict__ tm, const float* __restrict__ p) {
    __shared__ float sm[4];
    __shared__ float red;
    const int tid = threadIdx.x;  // 128 threads

    const float* src = (blockIdx.x < NS) ? (tm + (size_t)blockIdx.x * NS) : p;

    float m = -1e30f;
    #pragma unroll
    for (int k = 0; k < 4; k++) m = fmaxf(m, src[tid + 128 * k]);
    #pragma unroll
    for (int o = 16; o; o >>= 1) m = fmaxf(m, __shfl_xor_sync(~0u, m, o));
    if ((tid & 31) == 0) sm[tid >> 5] = m;
    __syncthreads();
    if (tid == 0) red = fmaxf(fmaxf(sm[0], sm[1]), fmaxf(sm[2], sm[3]));
    __syncthreads();
    m = red;

    float s = 0.f;
    #pragma unroll
    for (int k = 0; k < 4; k++) s += __expf(src[tid + 128 * k] - m);
    #pragma unroll
    for (int o = 16; o; o >>= 1) s += __shfl_xor_sync(~0u, s, o);
    if ((tid & 31) == 0) sm[tid >> 5] = s;
    __syncthreads();
    if (tid == 0) red = m + __logf(sm[0] + sm[1] + sm[2] + sm[3]);
    __syncthreads();
    const float lse = red;

    if (blockIdx.x < NS) {
        const int row = blockIdx.x;  // source state s
        #pragma unroll
        for (int k = 0; k < 4; k++) {
            int c = tid + 128 * k;   // dest state
            g_PT[(size_t)c * NS + row] = __expf(src[c] - lse);
        }
    } else {
        #pragma unroll
        for (int k = 0; k < 4; k++) {
            int i = tid + 128 * k;
            g_pi[i] = __expf(p[i] - lse);
        }
    }
}

// ===================== K3: gather E + reset barrier counters ====================
// NOTE: input_ids arrives as int32 (JAX downgrades int64 without x64 mode, and
// the harness dtype table has no int64). Clamp defensively against OOB.
__global__ void k_gather(const float* __restrict__ em, const int* __restrict__ ids) {
    const int bt = blockIdx.x;           // 0..2047
    if (bt == 0 && threadIdx.x < NB) g_cnt[threadIdx.x * 64] = 0;  // reset per launch
    int id = ids[bt];
    id = (id < 0) ? 0 : ((id >= NV) ? NV - 1 : id);
    const float* col = em + id;
    #pragma unroll
    for (int k = 0; k < 4; k++) {
        int s = threadIdx.x + 128 * k;   // blockDim = 128
        g_E[(size_t)bt * NS + s] = __expf(col[(size_t)s * NV] - g_lse_em[s]);
    }
}

// ===================== K4: persistent grouped scaled-forward recurrence =========
// 16 groups (one per batch) x 8 CTAs x 512 threads, classic launch (no clusters).
// Each CTA owns 64 output columns; its 64x512 P^T chunk lives in registers.
// Per step: LDG prev vector (L2) -> dot (64 FMA/thread) + butterfly (result +
// S_prev concurrently) -> scale -> STG 64-float chunk -> software group barrier
// (monotonic counter in L2: fence+atomicAdd release / volatile-poll+fence acquire).
__global__ void __launch_bounds__(512, 1) k_forward() {
    const int tid = threadIdx.x;
    const int w = tid >> 5;
    const int l = tid & 31;
    const int g = blockIdx.x >> 3;            // batch / group
    const int rank = blockIdx.x & 7;
    const int colbase = rank * 64 + w * 4;    // this warp's 4 output columns

    // --- P^T chunk into registers: P4[j][k] = PT[colbase+j][4l+128k .. +3] ---
    float4 P4[4][4];
    #pragma unroll
    for (int j = 0; j < 4; j++)
        #pragma unroll
        for (int k = 0; k < 4; k++)
            P4[j][k] = *(const float4*)&g_PT[(size_t)(colbase + j) * NS + 4 * l + 128 * k];

    const float* Eb = g_E + (size_t)g * NT * NS;
    unsigned* cnt = &g_cnt[g * 64];
    volatile unsigned* vcnt = cnt;

    // --- t = 0: only rank 0 fills v0 = pi * E0 (buffer is global, shared). ---
    if (rank == 0) {
        g_X[0][g][tid] = g_pi[tid] * Eb[tid];
        __threadfence();
    }
    __syncthreads();
    if (tid == 0) {
        atomicAdd(cnt, 1u);
        while (*vcnt < 8u) { }
    }
    __syncthreads();
    __threadfence();

    int par = 0;
    float L = 0.f;

    for (int t = 1; t < NT; t++) {
        // emission factors for this step's columns (independent load, issue early)
        float e = 0.f;
        if (l < 4) e = Eb[t * NS + colbase + l];

        const float* cur = g_X[par][g];
        float a0 = 0.f, a1 = 0.f, a2 = 0.f, a3 = 0.f;
        float ssA = 0.f, ssB = 0.f;           // S_prev partials (warp covers all 512 s)
        #pragma unroll
        for (int k = 0; k < 4; k++) {
            float4 a = *(const float4*)&cur[4 * l + 128 * k];
            a0 = fmaf(a.x, P4[0][k].x, fmaf(a.y, P4[0][k].y, fmaf(a.z, P4[0][k].z, fmaf(a.w, P4[0][k].w, a0))));
            a1 = fmaf(a.x, P4[1][k].x, fmaf(a.y, P4[1][k].y, fmaf(a.z, P4[1][k].z, fmaf(a.w, P4[1][k].w, a1))));
            a2 = fmaf(a.x, P4[2][k].x, fmaf(a.y, P4[2][k].y, fmaf(a.z, P4[2][k].z, fmaf(a.w, P4[2][k].w, a2))));
            a3 = fmaf(a.x, P4[3][k].x, fmaf(a.y, P4[3][k].y, fmaf(a.z, P4[3][k].z, fmaf(a.w, P4[3][k].w, a3))));
            ssA += a.x + a.y;
            ssB += a.z + a.w;
        }
        float ss = ssA + ssB;
        #pragma unroll
        for (int o = 16; o; o >>= 1) {
            a0 += __shfl_xor_sync(~0u, a0, o);
            a1 += __shfl_xor_sync(~0u, a1, o);
            a2 += __shfl_xor_sync(~0u, a2, o);
            a3 += __shfl_xor_sync(~0u, a3, o);
            ss += __shfl_xor_sync(~0u, ss, o);
        }
        // ss == S_{t-1}; identical across all warps & CTAs of the group
        if (rank == 0 && tid == 0) L += __logf(ss);
        const float invS = __fdividef(1.f, ss);

        const int nxt = par ^ 1;
        if (l < 4) {
            float acc = (l == 0) ? a0 : (l == 1) ? a1 : (l == 2) ? a2 : a3;
            g_X[nxt][g][colbase + l] = acc * invS * e;   // v_t chunk, written once
        }
        __threadfence();       // release our stores before signaling
        __syncthreads();
        if (tid == 0) {
            atomicAdd(cnt, 1u);                           // arrive
            const unsigned target = 8u * (unsigned)t + 8u;
            while (*vcnt < target) { }
        }
        __syncthreads();
        __threadfence();       // acquire: peers' chunks now visible
        par = nxt;
    }

    // --- final S_{T-1} term ---
    {
        const float* cur = g_X[par][g];
        float ss = 0.f;
        #pragma unroll
        for (int k = 0; k < 4; k++) {
            float4 a = *(const float4*)&cur[4 * l + 128 * k];
            ss += (a.x + a.y) + (a.z + a.w);
        }
        #pragma unroll
        for (int o = 16; o; o >>= 1) ss += __shfl_xor_sync(~0u, ss, o);
        if (rank == 0 && tid == 0) {
            L += __logf(ss);
            g_L[g] = L;
        }
    }
}

// ===================== K5: loss = -mean_b L[b] ===================================
__global__ void k_final(float* __restrict__ out) {
    if (threadIdx.x == 0) {
        float s = 0.f;
        #pragma unroll
        for (int i = 0; i < NB; i++) s += g_L[i];
        out[0] = -s / (float)NB;
    }
}

// ===================== launch ====================================================
extern "C" void kernel_launch(void* const* d_in, const int* in_sizes, int n_in,
                              void* d_out, int out_size) {
    const float* em = nullptr;
    const float* tm = nullptr;
    const float* p  = nullptr;
    const int* ids  = nullptr;
    for (int i = 0; i < n_in; i++) {
        if (in_sizes[i] == NB * NT)      ids = (const int*)d_in[i];
        else if (in_sizes[i] == NS * NV) em  = (const float*)d_in[i];
        else if (in_sizes[i] == NS * NS) tm  = (const float*)d_in[i];
        else if (in_sizes[i] == NS)      p   = (const float*)d_in[i];
    }

    k_lse_em<<<NS, 256>>>(em);
    k_tm_pi<<<NS + 1, 128>>>(tm, p);
    k_gather<<<NB * NT, 128>>>(em, ids);
    k_forward<<<NB * 8, 512>>>();
    k_final<<<1, 32>>>((float*)d_out);
}

// round 5
// speedup vs baseline: 1.1017x; 1.1017x over previous
#include <cuda_runtime.h>
#include <cstdint>

#define NS 512
#define NV 32000
#define NB 16
#define NT 128

// ---- scratch (no cudaMalloc allowed) ----
__device__ float g_lse_em[NS];
__device__ float g_pi[NS];
__device__ float g_PT[NS * NS];          // PT[c][s] = softmax(tm)[s][c]
__device__ float g_E[NB * NT * NS];      // E[b][t][s] = exp(log_em[s, x_bt])
__device__ float g_L[NB];                // per-batch log-likelihood
__device__ float g_X[2][NB][NS];         // per-group exchange buffers (double)
__device__ unsigned g_flag[NB][8 * 32];  // per-(group,CTA) epoch flags, 128B apart

// ---- release/acquire primitives (no full membars) ----
__device__ __forceinline__ void st_release(unsigned* p, unsigned v) {
    asm volatile("st.release.gpu.global.u32 [%0], %1;" :: "l"(p), "r"(v) : "memory");
}
__device__ __forceinline__ unsigned ld_acquire(const unsigned* p) {
    unsigned v;
    asm volatile("ld.acquire.gpu.global.u32 %0, [%1];" : "=r"(v) : "l"(p) : "memory");
    return v;
}

// ===================== K1: row logsumexp of em [512, 32000] =====================
__global__ void k_lse_em(const float* __restrict__ em) {
    const int row = blockIdx.x;
    const float4* r = (const float4*)(em + (size_t)row * NV);
    const int n4 = NV / 4;  // 8000

    __shared__ float sm[8];

    float m = -1e30f;
    for (int i = threadIdx.x; i < n4; i += blockDim.x) {
        float4 x = r[i];
        m = fmaxf(m, fmaxf(fmaxf(x.x, x.y), fmaxf(x.z, x.w)));
    }
    #pragma unroll
    for (int o = 16; o; o >>= 1) m = fmaxf(m, __shfl_xor_sync(~0u, m, o));
    if ((threadIdx.x & 31) == 0) sm[threadIdx.x >> 5] = m;
    __syncthreads();
    if (threadIdx.x < 32) {
        float mm = (threadIdx.x < (blockDim.x >> 5)) ? sm[threadIdx.x] : -1e30f;
        #pragma unroll
        for (int o = 4; o; o >>= 1) mm = fmaxf(mm, __shfl_xor_sync(~0u, mm, o));
        if (threadIdx.x == 0) sm[0] = mm;
    }
    __syncthreads();
    m = sm[0];
    __syncthreads();

    float s = 0.f;
    for (int i = threadIdx.x; i < n4; i += blockDim.x) {
        float4 x = r[i];
        s += __expf(x.x - m) + __expf(x.y - m) + __expf(x.z - m) + __expf(x.w - m);
    }
    #pragma unroll
    for (int o = 16; o; o >>= 1) s += __shfl_xor_sync(~0u, s, o);
    if ((threadIdx.x & 31) == 0) sm[threadIdx.x >> 5] = s;
    __syncthreads();
    if (threadIdx.x == 0) {
        float tot = 0.f;
        for (int wi = 0; wi < (blockDim.x >> 5); wi++) tot += sm[wi];
        g_lse_em[row] = m + __logf(tot);
    }
}

// ===================== K2: P^T = softmax(tm) transposed; pi = softmax(p) ========
__global__ void k_tm_pi(const float* __restrict__ tm, const float* __restrict__ p) {
    __shared__ float sm[4];
    __shared__ float red;
    const int tid = threadIdx.x;  // 128 threads

    const float* src = (blockIdx.x < NS) ? (tm + (size_t)blockIdx.x * NS) : p;

    float m = -1e30f;
    #pragma unroll
    for (int k = 0; k < 4; k++) m = fmaxf(m, src[tid + 128 * k]);
    #pragma unroll
    for (int o = 16; o; o >>= 1) m = fmaxf(m, __shfl_xor_sync(~0u, m, o));
    if ((tid & 31) == 0) sm[tid >> 5] = m;
    __syncthreads();
    if (tid == 0) red = fmaxf(fmaxf(sm[0], sm[1]), fmaxf(sm[2], sm[3]));
    __syncthreads();
    m = red;

    float s = 0.f;
    #pragma unroll
    for (int k = 0; k < 4; k++) s += __expf(src[tid + 128 * k] - m);
    #pragma unroll
    for (int o = 16; o; o >>= 1) s += __shfl_xor_sync(~0u, s, o);
    if ((tid & 31) == 0) sm[tid >> 5] = s;
    __syncthreads();
    if (tid == 0) red = m + __logf(sm[0] + sm[1] + sm[2] + sm[3]);
    __syncthreads();
    const float lse = red;

    if (blockIdx.x < NS) {
        const int row = blockIdx.x;  // source state s
        #pragma unroll
        for (int k = 0; k < 4; k++) {
            int c = tid + 128 * k;   // dest state
            g_PT[(size_t)c * NS + row] = __expf(src[c] - lse);
        }
    } else {
        #pragma unroll
        for (int k = 0; k < 4; k++) {
            int i = tid + 128 * k;
            g_pi[i] = __expf(p[i] - lse);
        }
    }
}

// ===================== K3: gather E + reset epoch flags =========================
// input_ids arrives as int32 (JAX default int without x64). Clamp defensively.
__global__ void k_gather(const float* __restrict__ em, const int* __restrict__ ids) {
    const int bt = blockIdx.x;           // 0..2047
    if (bt == 0 && threadIdx.x < NB * 8)
        g_flag[threadIdx.x >> 3][(threadIdx.x & 7) * 32] = 0;   // reset per launch
    int id = ids[bt];
    id = (id < 0) ? 0 : ((id >= NV) ? NV - 1 : id);
    const float* col = em + id;
    #pragma unroll
    for (int k = 0; k < 4; k++) {
        int s = threadIdx.x + 128 * k;   // blockDim = 128
        g_E[(size_t)bt * NS + s] = __expf(col[(size_t)s * NV] - g_lse_em[s]);
    }
}

// ===================== K4: persistent grouped scaled-forward recurrence =========
// 16 groups (one per batch) x 8 CTAs x 512 threads. Each CTA owns 64 output
// columns; its 64x512 P^T chunk lives in registers (P4[4][4] float4/thread).
// Per step: LDG prev vector (L2) -> dot (64 FMA/thread) + butterfly (cols +
// S_prev concurrently) -> scale -> STG 64-float chunk -> epoch-flag barrier:
// bar.sync + st.release(flag[rank]=t+1); waiters: lanes 0..7 ld.acquire-poll
// the 8 flags in parallel, then bar.sync. No membars, no atomics.
__global__ void __launch_bounds__(512, 1) k_forward() {
    const int tid = threadIdx.x;
    const int w = tid >> 5;
    const int l = tid & 31;
    const int g = blockIdx.x >> 3;            // batch / group
    const int rank = blockIdx.x & 7;
    const int colbase = rank * 64 + w * 4;    // this warp's 4 output columns

    // --- P^T chunk into registers: P4[j][k] = PT[colbase+j][4l+128k .. +3] ---
    float4 P4[4][4];
    #pragma unroll
    for (int j = 0; j < 4; j++)
        #pragma unroll
        for (int k = 0; k < 4; k++)
            P4[j][k] = *(const float4*)&g_PT[(size_t)(colbase + j) * NS + 4 * l + 128 * k];

    const float* Eb = g_E + (size_t)g * NT * NS;
    unsigned* flags = &g_flag[g][0];

    // --- t = 0: rank 0 fills v0 = pi * E0; everyone waits on flag[0] >= 1 ---
    if (rank == 0) {
        g_X[0][g][tid] = g_pi[tid] * Eb[tid];
        __syncthreads();
        if (tid == 0) st_release(&flags[0], 1u);
    }
    if (tid == 0) {
        while (ld_acquire(&flags[0]) < 1u) { }
    }
    __syncthreads();

    int par = 0;
    float L = 0.f;

    for (int t = 1; t < NT; t++) {
        // emission factors for this step's columns (independent load, issue early)
        float e = 0.f;
        if (l < 4) e = Eb[t * NS + colbase + l];

        const float* cur = g_X[par][g];
        float a0 = 0.f, a1 = 0.f, a2 = 0.f, a3 = 0.f;
        float ssA = 0.f, ssB = 0.f;           // S_prev partials (warp covers all 512 s)
        #pragma unroll
        for (int k = 0; k < 4; k++) {
            float4 a = *(const float4*)&cur[4 * l + 128 * k];
            a0 = fmaf(a.x, P4[0][k].x, fmaf(a.y, P4[0][k].y, fmaf(a.z, P4[0][k].z, fmaf(a.w, P4[0][k].w, a0))));
            a1 = fmaf(a.x, P4[1][k].x, fmaf(a.y, P4[1][k].y, fmaf(a.z, P4[1][k].z, fmaf(a.w, P4[1][k].w, a1))));
            a2 = fmaf(a.x, P4[2][k].x, fmaf(a.y, P4[2][k].y, fmaf(a.z, P4[2][k].z, fmaf(a.w, P4[2][k].w, a2))));
            a3 = fmaf(a.x, P4[3][k].x, fmaf(a.y, P4[3][k].y, fmaf(a.z, P4[3][k].z, fmaf(a.w, P4[3][k].w, a3))));
            ssA += a.x + a.y;
            ssB += a.z + a.w;
        }
        float ss = ssA + ssB;
        #pragma unroll
        for (int o = 16; o; o >>= 1) {
            a0 += __shfl_xor_sync(~0u, a0, o);
            a1 += __shfl_xor_sync(~0u, a1, o);
            a2 += __shfl_xor_sync(~0u, a2, o);
            a3 += __shfl_xor_sync(~0u, a3, o);
            ss += __shfl_xor_sync(~0u, ss, o);
        }
        // ss == S_{t-1}; identical across all warps & CTAs of the group
        if (rank == 0 && tid == 0) L += __logf(ss);
        const float invS = __fdividef(1.f, ss);

        const int nxt = par ^ 1;
        if (l < 4) {
            float acc = (l == 0) ? a0 : (l == 1) ? a1 : (l == 2) ? a2 : a3;
            g_X[nxt][g][colbase + l] = acc * invS * e;   // v_t chunk, written once
        }
        // arrive: CTA's stores (incl. chunk) happen-before the release store
        __syncthreads();
        if (tid == 0) st_release(&flags[rank * 32], (unsigned)(t + 1));
        // wait: lanes 0..7 each poll one peer flag; bar propagates the acquire
        if (tid < 8) {
            while (ld_acquire(&flags[tid * 32]) <= (unsigned)t) { }
        }
        __syncthreads();
        par = nxt;
    }

    // --- final S_{T-1} term ---
    {
        const float* cur = g_X[par][g];
        float ss = 0.f;
        #pragma unroll
        for (int k = 0; k < 4; k++) {
            float4 a = *(const float4*)&cur[4 * l + 128 * k];
            ss += (a.x + a.y) + (a.z + a.w);
        }
        #pragma unroll
        for (int o = 16; o; o >>= 1) ss += __shfl_xor_sync(~0u, ss, o);
        if (rank == 0 && tid == 0) {
            L += __logf(ss);
            g_L[g] = L;
        }
    }
}

// ===================== K5: loss = -mean_b L[b] ===================================
__global__ void k_final(float* __restrict__ out) {
    if (threadIdx.x == 0) {
        float s = 0.f;
        #pragma unroll
        for (int i = 0; i < NB; i++) s += g_L[i];
        out[0] = -s / (float)NB;
    }
}

// ===================== launch ====================================================
extern "C" void kernel_launch(void* const* d_in, const int* in_sizes, int n_in,
                              void* d_out, int out_size) {
    const float* em = nullptr;
    const float* tm = nullptr;
    const float* p  = nullptr;
    const int* ids  = nullptr;
    for (int i = 0; i < n_in; i++) {
        if (in_sizes[i] == NB * NT)      ids = (const int*)d_in[i];
        else if (in_sizes[i] == NS * NV) em  = (const float*)d_in[i];
        else if (in_sizes[i] == NS * NS) tm  = (const float*)d_in[i];
        else if (in_sizes[i] == NS)      p   = (const float*)d_in[i];
    }

    k_lse_em<<<NS, 256>>>(em);
    k_tm_pi<<<NS + 1, 128>>>(tm, p);
    k_gather<<<NB * NT, 128>>>(em, ids);
    k_forward<<<NB * 8, 512>>>();
    k_final<<<1, 32>>>((float*)d_out);
}

// round 6
// speedup vs baseline: 1.3243x; 1.2021x over previous
#include <cuda_runtime.h>
#include <cstdint>

#define NS 512
#define NV 32000
#define NB 16
#define NT 128

// ---- scratch (no cudaMalloc allowed) ----
__device__ float g_lse_em[NS];
__device__ float g_pi[NS];
__device__ float g_PT[NS * NS];          // PT[c][s] = softmax(tm)[s][c]
__device__ float g_E[NB * NT * NS];      // E[b][t][s] = exp(log_em[s, x_bt])
__device__ float g_L[NB];                // per-batch log-likelihood

// ---- helpers ----
__device__ __forceinline__ unsigned smem_u32(const void* p) {
    return (unsigned)__cvta_generic_to_shared(p);
}
__device__ __forceinline__ unsigned mapa_u32(unsigned local, unsigned rank) {
    unsigned r;
    asm("mapa.shared::cluster.u32 %0, %1, %2;" : "=r"(r) : "r"(local), "r"(rank));
    return r;
}
#define MBAR_INIT(mb, cnt) \
    asm volatile("mbarrier.init.shared.b64 [%0], %1;" :: "r"(mb), "r"(cnt) : "memory")
#define MBAR_EXPECT_TX(mb, bytes) \
    asm volatile("mbarrier.arrive.expect_tx.shared.b64 _, [%0], %1;" :: "r"(mb), "r"(bytes) : "memory")
#define MBAR_WAIT_CLUSTER(mb, parity) do {                                          \
    asm volatile("{\n\t.reg .pred P;\n\tW%=:\n\t"                                   \
        "mbarrier.try_wait.parity.acquire.cluster.shared::cta.b64 P, [%0], %1;\n\t" \
        "@!P bra W%=;\n\t}" :: "r"(mb), "r"(parity) : "memory");                    \
} while (0)
__device__ __forceinline__ void st_async_v4(unsigned raddr, float4 v, unsigned rmbar) {
    asm volatile(
        "st.async.shared::cluster.mbarrier::complete_tx::bytes.v4.f32 "
        "[%0], {%1, %2, %3, %4}, [%5];"
        :: "r"(raddr), "f"(v.x), "f"(v.y), "f"(v.z), "f"(v.w), "r"(rmbar) : "memory");
}

// ===================== K1: row logsumexp of em [512, 32000] =====================
__global__ void k_lse_em(const float* __restrict__ em) {
    const int row = blockIdx.x;
    const float4* r = (const float4*)(em + (size_t)row * NV);
    const int n4 = NV / 4;  // 8000

    __shared__ float sm[8];

    float m = -1e30f;
    for (int i = threadIdx.x; i < n4; i += blockDim.x) {
        float4 x = r[i];
        m = fmaxf(m, fmaxf(fmaxf(x.x, x.y), fmaxf(x.z, x.w)));
    }
    #pragma unroll
    for (int o = 16; o; o >>= 1) m = fmaxf(m, __shfl_xor_sync(~0u, m, o));
    if ((threadIdx.x & 31) == 0) sm[threadIdx.x >> 5] = m;
    __syncthreads();
    if (threadIdx.x < 32) {
        float mm = (threadIdx.x < (blockDim.x >> 5)) ? sm[threadIdx.x] : -1e30f;
        #pragma unroll
        for (int o = 4; o; o >>= 1) mm = fmaxf(mm, __shfl_xor_sync(~0u, mm, o));
        if (threadIdx.x == 0) sm[0] = mm;
    }
    __syncthreads();
    m = sm[0];
    __syncthreads();

    float s = 0.f;
    for (int i = threadIdx.x; i < n4; i += blockDim.x) {
        float4 x = r[i];
        s += __expf(x.x - m) + __expf(x.y - m) + __expf(x.z - m) + __expf(x.w - m);
    }
    #pragma unroll
    for (int o = 16; o; o >>= 1) s += __shfl_xor_sync(~0u, s, o);
    if ((threadIdx.x & 31) == 0) sm[threadIdx.x >> 5] = s;
    __syncthreads();
    if (threadIdx.x == 0) {
        float tot = 0.f;
        for (int wi = 0; wi < (blockDim.x >> 5); wi++) tot += sm[wi];
        g_lse_em[row] = m + __logf(tot);
    }
}

// ===================== K2: P^T = softmax(tm) transposed; pi = softmax(p) ========
__global__ void k_tm_pi(const float* __restrict__ tm, const float* __restrict__ p) {
    __shared__ float sm[4];
    __shared__ float red;
    const int tid = threadIdx.x;  // 128 threads

    const float* src = (blockIdx.x < NS) ? (tm + (size_t)blockIdx.x * NS) : p;

    float m = -1e30f;
    #pragma unroll
    for (int k = 0; k < 4; k++) m = fmaxf(m, src[tid + 128 * k]);
    #pragma unroll
    for (int o = 16; o; o >>= 1) m = fmaxf(m, __shfl_xor_sync(~0u, m, o));
    if ((tid & 31) == 0) sm[tid >> 5] = m;
    __syncthreads();
    if (tid == 0) red = fmaxf(fmaxf(sm[0], sm[1]), fmaxf(sm[2], sm[3]));
    __syncthreads();
    m = red;

    float s = 0.f;
    #pragma unroll
    for (int k = 0; k < 4; k++) s += __expf(src[tid + 128 * k] - m);
    #pragma unroll
    for (int o = 16; o; o >>= 1) s += __shfl_xor_sync(~0u, s, o);
    if ((tid & 31) == 0) sm[tid >> 5] = s;
    __syncthreads();
    if (tid == 0) red = m + __logf(sm[0] + sm[1] + sm[2] + sm[3]);
    __syncthreads();
    const float lse = red;

    if (blockIdx.x < NS) {
        const int row = blockIdx.x;  // source state s
        #pragma unroll
        for (int k = 0; k < 4; k++) {
            int c = tid + 128 * k;   // dest state
            g_PT[(size_t)c * NS + row] = __expf(src[c] - lse);
        }
    } else {
        #pragma unroll
        for (int k = 0; k < 4; k++) {
            int i = tid + 128 * k;
            g_pi[i] = __expf(p[i] - lse);
        }
    }
}

// ===================== K3: gather E[b][t][s] = exp(em[s, id] - lse_em[s]) =======
// input_ids arrives as int32 (JAX default int without x64). Clamp defensively.
__global__ void k_gather(const float* __restrict__ em, const int* __restrict__ ids) {
    const int bt = blockIdx.x;           // 0..2047
    int id = ids[bt];
    id = (id < 0) ? 0 : ((id >= NV) ? NV - 1 : id);
    const float* col = em + id;
    #pragma unroll
    for (int k = 0; k < 4; k++) {
        int s = threadIdx.x + 128 * k;   // blockDim = 128
        g_E[(size_t)bt * NS + s] = __expf(col[(size_t)s * NV] - g_lse_em[s]);
    }
}

// ===================== K4: clustered scaled-forward recurrence (DSMEM push) =====
// 16 clusters (one per batch) x 8 CTAs x 512 threads. Each CTA owns 64 output
// columns; its 64x512 P^T chunk lives in registers (P4[4][4] float4/thread).
// Per step: LDS prev vector (local smem) -> dot + butterfly (cols + S_prev) ->
// scale -> lanes 0..7 of each warp st.async the warp's 4-col float4 to all 8
// peers' smem slot (t&1) with tx-count on each peer's LOCAL mbarrier ->
// consumers try_wait their local mbarrier (LDS-speed poll, no L2 round trip).
__global__ void __cluster_dims__(8, 1, 1) __launch_bounds__(512, 1) k_forward() {
    __shared__ __align__(16) float buf[2][NS];
    __shared__ __align__(8) unsigned long long mbars[2];

    const int tid = threadIdx.x;
    const int w = tid >> 5;
    const int l = tid & 31;
    unsigned rank;
    asm("mov.u32 %0, %%cluster_ctarank;" : "=r"(rank));
    const int g = blockIdx.x >> 3;                 // batch / cluster id
    const int colbase = (int)rank * 64 + w * 4;    // this warp's 4 output columns

    // --- P^T chunk into registers: P4[j][k] = PT[colbase+j][4l+128k .. +3] ---
    float4 P4[4][4];
    #pragma unroll
    for (int j = 0; j < 4; j++)
        #pragma unroll
        for (int k = 0; k < 4; k++)
            P4[j][k] = *(const float4*)&g_PT[(size_t)(colbase + j) * NS + 4 * l + 128 * k];

    const unsigned mb0 = smem_u32(&mbars[0]);
    const unsigned mb1 = smem_u32(&mbars[1]);
    if (tid == 0) { MBAR_INIT(mb0, 1); MBAR_INIT(mb1, 1); }

    const float* Eb = g_E + (size_t)g * NT * NS;

    // --- t = 0: every CTA computes the full v0 = pi * E0 locally ---
    buf[0][tid] = g_pi[tid] * Eb[tid];
    __syncthreads();
    // peers' mbarriers must be initialized before any st.async targets them
    asm volatile("barrier.cluster.arrive.aligned;" ::: "memory");
    asm volatile("barrier.cluster.wait.aligned;"   ::: "memory");

    // --- per-lane remote addresses (lanes 0..7 push to peer = lane index) ---
    unsigned rbuf = 0, rmb0 = 0, rmb1 = 0;
    if (l < 8) {
        rbuf = mapa_u32(smem_u32(&buf[0][0]), (unsigned)l);
        rmb0 = mapa_u32(mb0, (unsigned)l);
        rmb1 = mapa_u32(mb1, (unsigned)l);
    }

    int ph0 = 0, ph1 = 0;
    float L = 0.f;

    for (int t = 1; t < NT; t++) {
        // wait for v_{t-1} (pushed into our slot (t-1)&1); t==1 data is local
        if (t >= 2) {
            if ((t - 1) & 1) { MBAR_WAIT_CLUSTER(mb1, ph1); ph1 ^= 1; }
            else             { MBAR_WAIT_CLUSTER(mb0, ph0); ph0 ^= 1; }
        }
        // arm this step's receive barrier (2048 B = 8 ranks x 16 warps x 16 B)
        if (tid == 0) MBAR_EXPECT_TX((t & 1) ? mb1 : mb0, 2048u);

        // emission factors for this warp's 4 columns
        const float4 e4 = *(const float4*)&Eb[t * NS + colbase];

        const float* cur = buf[(t - 1) & 1];
        float a0 = 0.f, a1 = 0.f, a2 = 0.f, a3 = 0.f;
        float ssA = 0.f, ssB = 0.f;           // S_prev partials (warp covers all 512 s)
        #pragma unroll
        for (int k = 0; k < 4; k++) {
            float4 a = *(const float4*)&cur[4 * l + 128 * k];
            a0 = fmaf(a.x, P4[0][k].x, fmaf(a.y, P4[0][k].y, fmaf(a.z, P4[0][k].z, fmaf(a.w, P4[0][k].w, a0))));
            a1 = fmaf(a.x, P4[1][k].x, fmaf(a.y, P4[1][k].y, fmaf(a.z, P4[1][k].z, fmaf(a.w, P4[1][k].w, a1))));
            a2 = fmaf(a.x, P4[2][k].x, fmaf(a.y, P4[2][k].y, fmaf(a.z, P4[2][k].z, fmaf(a.w, P4[2][k].w, a2))));
            a3 = fmaf(a.x, P4[3][k].x, fmaf(a.y, P4[3][k].y, fmaf(a.z, P4[3][k].z, fmaf(a.w, P4[3][k].w, a3))));
            ssA += a.x + a.y;
            ssB += a.z + a.w;
        }
        float ss = ssA + ssB;
        #pragma unroll
        for (int o = 16; o; o >>= 1) {
            a0 += __shfl_xor_sync(~0u, a0, o);
            a1 += __shfl_xor_sync(~0u, a1, o);
            a2 += __shfl_xor_sync(~0u, a2, o);
            a3 += __shfl_xor_sync(~0u, a3, o);
            ss += __shfl_xor_sync(~0u, ss, o);
        }
        // ss == S_{t-1}; identical across all warps & CTAs of the cluster
        if (rank == 0 && tid == 0) L += __logf(ss);
        const float invS = __fdividef(1.f, ss);

        // push this warp's 4 scaled columns to all 8 CTAs (lane r -> peer r)
        if (l < 8) {
            float4 v;
            v.x = a0 * invS * e4.x;
            v.y = a1 * invS * e4.y;
            v.z = a2 * invS * e4.z;
            v.w = a3 * invS * e4.w;
            const unsigned daddr = rbuf + (unsigned)(((t & 1) * NS + colbase) * 4);
            st_async_v4(daddr, v, (t & 1) ? rmb1 : rmb0);
        }
    }

    // --- final S_{T-1} term: v_127 lives in slot 1 / mbar 1 ---
    MBAR_WAIT_CLUSTER(mb1, ph1);
    {
        const float* cur = buf[1];
        float ss = 0.f;
        #pragma unroll
        for (int k = 0; k < 4; k++) {
            float4 a = *(const float4*)&cur[4 * l + 128 * k];
            ss += (a.x + a.y) + (a.z + a.w);
        }
        #pragma unroll
        for (int o = 16; o; o >>= 1) ss += __shfl_xor_sync(~0u, ss, o);
        if (rank == 0 && tid == 0) {
            L += __logf(ss);
            g_L[g] = L;
        }
    }
    // no CTA may exit while peers might still push into its smem: v127 push was
    // the last remote op, and everyone waited on it above. Still, align exits.
    asm volatile("barrier.cluster.arrive.aligned;" ::: "memory");
    asm volatile("barrier.cluster.wait.aligned;"   ::: "memory");
}

// ===================== K5: loss = -mean_b L[b] ===================================
__global__ void k_final(float* __restrict__ out) {
    if (threadIdx.x == 0) {
        float s = 0.f;
        #pragma unroll
        for (int i = 0; i < NB; i++) s += g_L[i];
        out[0] = -s / (float)NB;
    }
}

// ===================== launch ====================================================
extern "C" void kernel_launch(void* const* d_in, const int* in_sizes, int n_in,
                              void* d_out, int out_size) {
    const float* em = nullptr;
    const float* tm = nullptr;
    const float* p  = nullptr;
    const int* ids  = nullptr;
    for (int i = 0; i < n_in; i++) {
        if (in_sizes[i] == NB * NT)      ids = (const int*)d_in[i];
        else if (in_sizes[i] == NS * NV) em  = (const float*)d_in[i];
        else if (in_sizes[i] == NS * NS) tm  = (const float*)d_in[i];
        else if (in_sizes[i] == NS)      p   = (const float*)d_in[i];
    }

    k_lse_em<<<NS, 256>>>(em);
    k_tm_pi<<<NS + 1, 128>>>(tm, p);
    k_gather<<<NB * NT, 128>>>(em, ids);

    // cluster launch via cudaLaunchKernelEx (bare <<<>>> cluster launches were
    // rejected synchronously with cudaErrorInvalidAddressSpace in R1/R2)
    {
        cudaLaunchConfig_t cfg = {};
        cfg.gridDim  = dim3(NB * 8, 1, 1);
        cfg.blockDim = dim3(512, 1, 1);
        cfg.dynamicSmemBytes = 0;
        cfg.stream = 0;
        cudaLaunchAttribute attrs[1];
        attrs[0].id = cudaLaunchAttributeClusterDimension;
        attrs[0].val.clusterDim.x = 8;
        attrs[0].val.clusterDim.y = 1;
        attrs[0].val.clusterDim.z = 1;
        cfg.attrs = attrs;
        cfg.numAttrs = 1;
        cudaLaunchKernelEx(&cfg, k_forward);
    }

    k_final<<<1, 32>>>((float*)d_out);
}

// round 7
// speedup vs baseline: 1.3846x; 1.0455x over previous
#include <cuda_runtime.h>
#include <cstdint>

#define NS 512
#define NV 32000
#define NB 16
#define NT 128

// ---- scratch (no cudaMalloc allowed) ----
__device__ float g_lse_em[NS];
__device__ float g_pi[NS];
__device__ float g_PT[NS * NS];          // PT[c][s] = softmax(tm)[s][c]
__device__ float g_E[NB * NT * NS];      // E[b][t][s] = exp(log_em[s, x_bt])
__device__ float g_L[NB];                // per-batch log-likelihood

// ---- helpers ----
__device__ __forceinline__ unsigned smem_u32(const void* p) {
    return (unsigned)__cvta_generic_to_shared(p);
}
__device__ __forceinline__ unsigned mapa_u32(unsigned local, unsigned rank) {
    unsigned r;
    asm("mapa.shared::cluster.u32 %0, %1, %2;" : "=r"(r) : "r"(local), "r"(rank));
    return r;
}
#define MBAR_INIT(mb, cnt) \
    asm volatile("mbarrier.init.shared.b64 [%0], %1;" :: "r"(mb), "r"(cnt) : "memory")
#define MBAR_EXPECT_TX(mb, bytes) \
    asm volatile("mbarrier.arrive.expect_tx.shared.b64 _, [%0], %1;" :: "r"(mb), "r"(bytes) : "memory")
// HW-sleep wait: suspend-time hint keeps spinning warps OFF the SMEM port so the
// incoming DSMEM transactions + phase update are not contended (wakeup ~60 cyc).
#define MBAR_WAIT_CLUSTER(mb, parity) do {                                                       \
    asm volatile("{\n\t.reg .pred P;\n\tW%=:\n\t"                                                \
        "mbarrier.try_wait.parity.acquire.cluster.shared::cta.b64 P, [%0], %1, 0x989680;\n\t"    \
        "@!P bra W%=;\n\t}" :: "r"(mb), "r"(parity) : "memory");                                 \
} while (0)
__device__ __forceinline__ void st_async_v4(unsigned raddr, float4 v, unsigned rmbar) {
    asm volatile(
        "st.async.shared::cluster.mbarrier::complete_tx::bytes.v4.f32 "
        "[%0], {%1, %2, %3, %4}, [%5];"
        :: "r"(raddr), "f"(v.x), "f"(v.y), "f"(v.z), "f"(v.w), "r"(rmbar) : "memory");
}
// packed f32x2 math (FFMA2/FADD2 — only reachable via PTX)
#define FMA2(d, a, b, c) \
    asm("fma.rn.f32x2 %0, %1, %2, %3;" : "=l"(d) : "l"(a), "l"(b), "l"(c))
#define ADD2(d, a, b) \
    asm("add.rn.f32x2 %0, %1, %2;" : "=l"(d) : "l"(a), "l"(b))
__device__ __forceinline__ float hadd2(unsigned long long v) {
    float lo, hi;
    asm("mov.b64 {%0, %1}, %2;" : "=f"(lo), "=f"(hi) : "l"(v));
    return lo + hi;
}

// ===================== K1: row logsumexp of em [512, 32000] =====================
__global__ void k_lse_em(const float* __restrict__ em) {
    const int row = blockIdx.x;
    const float4* r = (const float4*)(em + (size_t)row * NV);
    const int n4 = NV / 4;  // 8000

    __shared__ float sm[8];

    float m = -1e30f;
    for (int i = threadIdx.x; i < n4; i += blockDim.x) {
        float4 x = r[i];
        m = fmaxf(m, fmaxf(fmaxf(x.x, x.y), fmaxf(x.z, x.w)));
    }
    #pragma unroll
    for (int o = 16; o; o >>= 1) m = fmaxf(m, __shfl_xor_sync(~0u, m, o));
    if ((threadIdx.x & 31) == 0) sm[threadIdx.x >> 5] = m;
    __syncthreads();
    if (threadIdx.x < 32) {
        float mm = (threadIdx.x < (blockDim.x >> 5)) ? sm[threadIdx.x] : -1e30f;
        #pragma unroll
        for (int o = 4; o; o >>= 1) mm = fmaxf(mm, __shfl_xor_sync(~0u, mm, o));
        if (threadIdx.x == 0) sm[0] = mm;
    }
    __syncthreads();
    m = sm[0];
    __syncthreads();

    float s = 0.f;
    for (int i = threadIdx.x; i < n4; i += blockDim.x) {
        float4 x = r[i];
        s += __expf(x.x - m) + __expf(x.y - m) + __expf(x.z - m) + __expf(x.w - m);
    }
    #pragma unroll
    for (int o = 16; o; o >>= 1) s += __shfl_xor_sync(~0u, s, o);
    if ((threadIdx.x & 31) == 0) sm[threadIdx.x >> 5] = s;
    __syncthreads();
    if (threadIdx.x == 0) {
        float tot = 0.f;
        for (int wi = 0; wi < (blockDim.x >> 5); wi++) tot += sm[wi];
        g_lse_em[row] = m + __logf(tot);
    }
}

// ===================== K2: P^T = softmax(tm) transposed; pi = softmax(p) ========
__global__ void k_tm_pi(const float* __restrict__ tm, const float* __restrict__ p) {
    __shared__ float sm[4];
    __shared__ float red;
    const int tid = threadIdx.x;  // 128 threads

    const float* src = (blockIdx.x < NS) ? (tm + (size_t)blockIdx.x * NS) : p;

    float m = -1e30f;
    #pragma unroll
    for (int k = 0; k < 4; k++) m = fmaxf(m, src[tid + 128 * k]);
    #pragma unroll
    for (int o = 16; o; o >>= 1) m = fmaxf(m, __shfl_xor_sync(~0u, m, o));
    if ((tid & 31) == 0) sm[tid >> 5] = m;
    __syncthreads();
    if (tid == 0) red = fmaxf(fmaxf(sm[0], sm[1]), fmaxf(sm[2], sm[3]));
    __syncthreads();
    m = red;

    float s = 0.f;
    #pragma unroll
    for (int k = 0; k < 4; k++) s += __expf(src[tid + 128 * k] - m);
    #pragma unroll
    for (int o = 16; o; o >>= 1) s += __shfl_xor_sync(~0u, s, o);
    if ((tid & 31) == 0) sm[tid >> 5] = s;
    __syncthreads();
    if (tid == 0) red = m + __logf(sm[0] + sm[1] + sm[2] + sm[3]);
    __syncthreads();
    const float lse = red;

    if (blockIdx.x < NS) {
        const int row = blockIdx.x;  // source state s
        #pragma unroll
        for (int k = 0; k < 4; k++) {
            int c = tid + 128 * k;   // dest state
            g_PT[(size_t)c * NS + row] = __expf(src[c] - lse);
        }
    } else {
        #pragma unroll
        for (int k = 0; k < 4; k++) {
            int i = tid + 128 * k;
            g_pi[i] = __expf(p[i] - lse);
        }
    }
}

// ===================== K3: gather E[b][t][s] = exp(em[s, id] - lse_em[s]) =======
// input_ids arrives as int32 (JAX default int without x64). Clamp defensively.
__global__ void k_gather(const float* __restrict__ em, const int* __restrict__ ids) {
    const int bt = blockIdx.x;           // 0..2047
    int id = ids[bt];
    id = (id < 0) ? 0 : ((id >= NV) ? NV - 1 : id);
    const float* col = em + id;
    #pragma unroll
    for (int k = 0; k < 4; k++) {
        int s = threadIdx.x + 128 * k;   // blockDim = 128
        g_E[(size_t)bt * NS + s] = __expf(col[(size_t)s * NV] - g_lse_em[s]);
    }
}

// ===================== K4: clustered scaled-forward recurrence (DSMEM push) =====
// 16 clusters (one per batch) x 8 CTAs x 512 threads. Each CTA owns 64 output
// columns; its 64x512 P^T chunk lives in packed f32x2 registers.
// Per step: sleep-wait local mbarrier -> packed dot (32 FFMA2/thread) + packed
// S-sum -> butterfly (4 cols + S) -> scale -> lanes 0..7 st.async the warp's
// 4-col float4 to all 8 peers' smem slot (t&1), tx-count on each peer's LOCAL
// mbarrier. Next-step emission factors prefetched one iteration ahead.
__global__ void __cluster_dims__(8, 1, 1) __launch_bounds__(512, 1) k_forward() {
    __shared__ __align__(16) float buf[2][NS];
    __shared__ __align__(8) unsigned long long mbars[2];

    const int tid = threadIdx.x;
    const int l = tid & 31;
    unsigned rank;
    asm("mov.u32 %0, %%cluster_ctarank;" : "=r"(rank));
    const int g = blockIdx.x >> 3;                        // batch / cluster id
    const int colbase = (int)rank * 64 + (tid >> 5) * 4;  // this warp's 4 columns

    // --- P^T chunk into packed registers:
    // Pa[j][k] = pair PT[colbase+j][4l+128k+{0,1}], Pb = +{2,3} ---
    unsigned long long Pa[4][4], Pb[4][4];
    #pragma unroll
    for (int j = 0; j < 4; j++)
        #pragma unroll
        for (int k = 0; k < 4; k++) {
            ulonglong2 pp = *(const ulonglong2*)&g_PT[(size_t)(colbase + j) * NS + 4 * l + 128 * k];
            Pa[j][k] = pp.x;
            Pb[j][k] = pp.y;
        }

    const unsigned mb0 = smem_u32(&mbars[0]);
    const unsigned mb1 = smem_u32(&mbars[1]);
    if (tid == 0) { MBAR_INIT(mb0, 1); MBAR_INIT(mb1, 1); }

    const float* Eb = g_E + (size_t)g * NT * NS;

    // --- t = 0: every CTA computes the full v0 = pi * E0 locally ---
    buf[0][tid] = g_pi[tid] * Eb[tid];
    __syncthreads();
    // peers' mbarriers must be initialized before any st.async targets them
    asm volatile("barrier.cluster.arrive.aligned;" ::: "memory");
    asm volatile("barrier.cluster.wait.aligned;"   ::: "memory");

    // --- per-lane remote addresses (lanes 0..7 push to peer = lane index) ---
    unsigned rbuf = 0, rmb0 = 0, rmb1 = 0;
    if (l < 8) {
        rbuf = mapa_u32(smem_u32(&buf[0][0]), (unsigned)l);
        rmb0 = mapa_u32(mb0, (unsigned)l);
        rmb1 = mapa_u32(mb1, (unsigned)l);
    }

    int ph0 = 0, ph1 = 0;
    float L = 0.f;
    float4 e4 = *(const float4*)&Eb[1 * NS + colbase];   // emission for t=1

    for (int t = 1; t < NT; t++) {
        // wait for v_{t-1} (pushed into our slot (t-1)&1); t==1 data is local
        if (t >= 2) {
            if ((t - 1) & 1) { MBAR_WAIT_CLUSTER(mb1, ph1); ph1 ^= 1; }
            else             { MBAR_WAIT_CLUSTER(mb0, ph0); ph0 ^= 1; }
        }
        // arm this step's receive barrier (2048 B = 8 ranks x 16 warps x 16 B)
        if (tid == 0) MBAR_EXPECT_TX((t & 1) ? mb1 : mb0, 2048u);

        // prefetch NEXT step's emission factors (off critical path)
        const int tn = (t + 1 < NT) ? t + 1 : t;
        const float4 e4n = *(const float4*)&Eb[tn * NS + colbase];

        // packed dot over the 512-vector + packed S_prev sum
        const float* cur = buf[(t - 1) & 1];
        unsigned long long acc0 = 0, acc1 = 0, acc2 = 0, acc3 = 0, ssp = 0;
        #pragma unroll
        for (int k = 0; k < 4; k++) {
            ulonglong2 aa = *(const ulonglong2*)&cur[4 * l + 128 * k];
            FMA2(acc0, aa.x, Pa[0][k], acc0); FMA2(acc0, aa.y, Pb[0][k], acc0);
            FMA2(acc1, aa.x, Pa[1][k], acc1); FMA2(acc1, aa.y, Pb[1][k], acc1);
            FMA2(acc2, aa.x, Pa[2][k], acc2); FMA2(acc2, aa.y, Pb[2][k], acc2);
            FMA2(acc3, aa.x, Pa[3][k], acc3); FMA2(acc3, aa.y, Pb[3][k], acc3);
            ADD2(ssp, ssp, aa.x); ADD2(ssp, ssp, aa.y);
        }
        float a0 = hadd2(acc0), a1 = hadd2(acc1), a2 = hadd2(acc2), a3 = hadd2(acc3);
        float ss = hadd2(ssp);
        #pragma unroll
        for (int o = 16; o; o >>= 1) {
            a0 += __shfl_xor_sync(~0u, a0, o);
            a1 += __shfl_xor_sync(~0u, a1, o);
            a2 += __shfl_xor_sync(~0u, a2, o);
            a3 += __shfl_xor_sync(~0u, a3, o);
            ss += __shfl_xor_sync(~0u, ss, o);
        }
        // ss == S_{t-1}; identical across all warps & CTAs of the cluster
        const float invS = __fdividef(1.f, ss);

        // push FIRST (critical path), bookkeeping after
        if (l < 8) {
            float4 v;
            v.x = a0 * invS * e4.x;
            v.y = a1 * invS * e4.y;
            v.z = a2 * invS * e4.z;
            v.w = a3 * invS * e4.w;
            const unsigned daddr = rbuf + (unsigned)(((t & 1) * NS + colbase) * 4);
            st_async_v4(daddr, v, (t & 1) ? rmb1 : rmb0);
        }
        if (rank == 0 && tid == 0) L += __logf(ss);
        e4 = e4n;
    }

    // --- final S_{T-1} term: v_127 lives in slot 1 / mbar 1 ---
    MBAR_WAIT_CLUSTER(mb1, ph1);
    {
        const float* cur = buf[1];
        unsigned long long ssp = 0;
        #pragma unroll
        for (int k = 0; k < 4; k++) {
            ulonglong2 aa = *(const ulonglong2*)&cur[4 * l + 128 * k];
            ADD2(ssp, ssp, aa.x); ADD2(ssp, ssp, aa.y);
        }
        float ss = hadd2(ssp);
        #pragma unroll
        for (int o = 16; o; o >>= 1) ss += __shfl_xor_sync(~0u, ss, o);
        if (rank == 0 && tid == 0) {
            L += __logf(ss);
            g_L[g] = L;
        }
    }
    // align exits: no CTA leaves while a peer could still target its smem
    asm volatile("barrier.cluster.arrive.aligned;" ::: "memory");
    asm volatile("barrier.cluster.wait.aligned;"   ::: "memory");
}

// ===================== K5: loss = -mean_b L[b] ===================================
__global__ void k_final(float* __restrict__ out) {
    if (threadIdx.x == 0) {
        float s = 0.f;
        #pragma unroll
        for (int i = 0; i < NB; i++) s += g_L[i];
        out[0] = -s / (float)NB;
    }
}

// ===================== launch ====================================================
extern "C" void kernel_launch(void* const* d_in, const int* in_sizes, int n_in,
                              void* d_out, int out_size) {
    const float* em = nullptr;
    const float* tm = nullptr;
    const float* p  = nullptr;
    const int* ids  = nullptr;
    for (int i = 0; i < n_in; i++) {
        if (in_sizes[i] == NB * NT)      ids = (const int*)d_in[i];
        else if (in_sizes[i] == NS * NV) em  = (const float*)d_in[i];
        else if (in_sizes[i] == NS * NS) tm  = (const float*)d_in[i];
        else if (in_sizes[i] == NS)      p   = (const float*)d_in[i];
    }

    k_lse_em<<<NS, 256>>>(em);
    k_tm_pi<<<NS + 1, 128>>>(tm, p);
    k_gather<<<NB * NT, 128>>>(em, ids);

    {
        cudaLaunchConfig_t cfg = {};
        cfg.gridDim  = dim3(NB * 8, 1, 1);
        cfg.blockDim = dim3(512, 1, 1);
        cfg.dynamicSmemBytes = 0;
        cfg.stream = 0;
        cudaLaunchAttribute attrs[1];
        attrs[0].id = cudaLaunchAttributeClusterDimension;
        attrs[0].val.clusterDim.x = 8;
        attrs[0].val.clusterDim.y = 1;
        attrs[0].val.clusterDim.z = 1;
        cfg.attrs = attrs;
        cfg.numAttrs = 1;
        cudaLaunchKernelEx(&cfg, k_forward);
    }

    k_final<<<1, 32>>>((float*)d_out);
}